// round 1
// baseline (speedup 1.0000x reference)
#include <cuda_runtime.h>
#include <math.h>

// ---------------------------------------------------------------------------
// BlipAttention: single-head attention over full C=768.
//   B=32, N=1024, C=768
//   qkv   = x @ qkv_w + qkv_b            (32768 x 2304)
//   S     = Q @ K^T / sqrt(C)            (32 x 1024 x 1024)
//   P     = softmax(S, axis=-1)
//   O     = P @ V                        stored TRANSPOSED per batch (C x N)
//   out   = reinterp(OT as (N,C)) @ proj_w + proj_b
// Scratch in __device__ globals (no allocation allowed).
// ---------------------------------------------------------------------------

__device__ float g_qkv[32u * 1024u * 2304u];     // ~302 MB
__device__ float g_scores[32u * 1024u * 1024u];  // ~134 MB
__device__ float g_ot[32u * 1024u * 768u];       // ~100 MB

// ---------------------------------------------------------------------------
// Generic fp32 SGEMM, 128x128 tile, BK=8, 256 threads, 8x8 per-thread tile.
// All problem dims here are exact multiples of the tile -> no bounds checks.
//  TRANSB: B operand is row-major [N,K] (we compute A * B^T)
//  TSTORE: store C transposed: C[n*ldc + m]  (used to fold the reshape)
//  BIAS  : add bias[n]
// ---------------------------------------------------------------------------
template <bool TRANSB, bool TSTORE, bool BIAS>
__global__ __launch_bounds__(256, 1) void sgemm128(
    const float* __restrict__ A, const float* __restrict__ Bm,
    const float* __restrict__ bias, float* __restrict__ Cm,
    int K, int lda, int ldb, int ldc, float alpha,
    long strideA, long strideB, long strideC)
{
    __shared__ float As[8][128];
    __shared__ float Bs[8][128];

    const int bz = blockIdx.z;
    A  += (long)bz * strideA;
    Bm += (long)bz * strideB;
    Cm += (long)bz * strideC;

    const int tid = threadIdx.x;
    const int tx = tid & 15;        // n direction (x8)
    const int ty = tid >> 4;        // m direction (x8)
    const int m0 = blockIdx.y * 128;
    const int n0 = blockIdx.x * 128;

    // A/B^T tile loads: one float4 per thread: row = tid>>1, k-quad = tid&1
    const int arow = tid >> 1;
    const int akq  = (tid & 1) * 4;
    // B (NN) tile loads: row k = tid>>5, col quad = (tid&31)*4
    const int bkrow = tid >> 5;
    const int bcol  = (tid & 31) * 4;

    float acc[8][8];
#pragma unroll
    for (int i = 0; i < 8; i++)
#pragma unroll
        for (int j = 0; j < 8; j++) acc[i][j] = 0.f;

    for (int k0 = 0; k0 < K; k0 += 8) {
        float4 av = *reinterpret_cast<const float4*>(
            &A[(long)(m0 + arow) * lda + k0 + akq]);
        As[akq + 0][arow] = av.x;
        As[akq + 1][arow] = av.y;
        As[akq + 2][arow] = av.z;
        As[akq + 3][arow] = av.w;

        if (TRANSB) {
            float4 bv = *reinterpret_cast<const float4*>(
                &Bm[(long)(n0 + arow) * ldb + k0 + akq]);
            Bs[akq + 0][arow] = bv.x;
            Bs[akq + 1][arow] = bv.y;
            Bs[akq + 2][arow] = bv.z;
            Bs[akq + 3][arow] = bv.w;
        } else {
            float4 bv = *reinterpret_cast<const float4*>(
                &Bm[(long)(k0 + bkrow) * ldb + n0 + bcol]);
            *reinterpret_cast<float4*>(&Bs[bkrow][bcol]) = bv;
        }
        __syncthreads();

#pragma unroll
        for (int kk = 0; kk < 8; kk++) {
            float ar[8], br[8];
#pragma unroll
            for (int i = 0; i < 8; i++) ar[i] = As[kk][ty * 8 + i];
#pragma unroll
            for (int j = 0; j < 8; j++) br[j] = Bs[kk][tx * 8 + j];
#pragma unroll
            for (int i = 0; i < 8; i++)
#pragma unroll
                for (int j = 0; j < 8; j++)
                    acc[i][j] = fmaf(ar[i], br[j], acc[i][j]);
        }
        __syncthreads();
    }

    // Epilogue
#pragma unroll
    for (int i = 0; i < 8; i++) {
        const int m = m0 + ty * 8 + i;
        if (TSTORE) {
#pragma unroll
            for (int j = 0; j < 8; j++) {
                const int n = n0 + tx * 8 + j;
                float v = acc[i][j] * alpha;
                if (BIAS) v += bias[n];
                Cm[(long)n * ldc + m] = v;
            }
        } else {
#pragma unroll
            for (int jq = 0; jq < 2; jq++) {
                const int n = n0 + tx * 8 + jq * 4;
                float4 v;
                v.x = acc[i][jq * 4 + 0] * alpha;
                v.y = acc[i][jq * 4 + 1] * alpha;
                v.z = acc[i][jq * 4 + 2] * alpha;
                v.w = acc[i][jq * 4 + 3] * alpha;
                if (BIAS) {
                    v.x += bias[n + 0];
                    v.y += bias[n + 1];
                    v.z += bias[n + 2];
                    v.w += bias[n + 3];
                }
                *reinterpret_cast<float4*>(&Cm[(long)m * ldc + n]) = v;
            }
        }
    }
}

// ---------------------------------------------------------------------------
// Row softmax, in place: 32768 rows of 1024 floats. 256 threads, 4 per thread.
// ---------------------------------------------------------------------------
__global__ __launch_bounds__(256) void softmax_rows(float* __restrict__ S)
{
    const long row = blockIdx.x;
    float4* p = reinterpret_cast<float4*>(S + row * 1024);
    const int tid = threadIdx.x;

    float4 v = p[tid];
    float m = fmaxf(fmaxf(v.x, v.y), fmaxf(v.z, v.w));
#pragma unroll
    for (int o = 16; o > 0; o >>= 1)
        m = fmaxf(m, __shfl_xor_sync(0xffffffffu, m, o));

    __shared__ float redm[8];
    __shared__ float reds[8];
    if ((tid & 31) == 0) redm[tid >> 5] = m;
    __syncthreads();
    float rm = redm[0];
#pragma unroll
    for (int i = 1; i < 8; i++) rm = fmaxf(rm, redm[i]);

    v.x = __expf(v.x - rm);
    v.y = __expf(v.y - rm);
    v.z = __expf(v.z - rm);
    v.w = __expf(v.w - rm);

    float s = v.x + v.y + v.z + v.w;
#pragma unroll
    for (int o = 16; o > 0; o >>= 1)
        s += __shfl_xor_sync(0xffffffffu, s, o);
    if ((tid & 31) == 0) reds[tid >> 5] = s;
    __syncthreads();
    float rs = 0.f;
#pragma unroll
    for (int i = 0; i < 8; i++) rs += reds[i];

    const float inv = 1.f / rs;
    v.x *= inv; v.y *= inv; v.z *= inv; v.w *= inv;
    p[tid] = v;
}

// ---------------------------------------------------------------------------
extern "C" void kernel_launch(void* const* d_in, const int* in_sizes, int n_in,
                              void* d_out, int out_size)
{
    const float* x      = (const float*)d_in[0];
    const float* qkv_w  = (const float*)d_in[1];
    const float* qkv_b  = (const float*)d_in[2];
    const float* proj_w = (const float*)d_in[3];
    const float* proj_b = (const float*)d_in[4];
    float* out = (float*)d_out;

    float *qkv, *sc, *ot;
    cudaGetSymbolAddress((void**)&qkv, g_qkv);
    cudaGetSymbolAddress((void**)&sc,  g_scores);
    cudaGetSymbolAddress((void**)&ot,  g_ot);

    const float scale = 1.0f / sqrtf(768.0f);

    // 1) QKV = X @ W + b : M=32768, N=2304, K=768 (NN + bias)
    sgemm128<false, false, true><<<dim3(2304 / 128, 32768 / 128, 1), 256>>>(
        x, qkv_w, qkv_b, qkv, 768, 768, 2304, 2304, 1.0f, 0, 0, 0);

    // 2) S = Q @ K^T * scale : per-batch M=1024, N=1024, K=768 (NT)
    sgemm128<true, false, false><<<dim3(8, 8, 32), 256>>>(
        qkv + 0, qkv + 768, nullptr, sc, 768, 2304, 2304, 1024, scale,
        1024L * 2304, 1024L * 2304, 1024L * 1024);

    // 3) softmax over rows
    softmax_rows<<<32 * 1024, 256>>>(sc);

    // 4) OT[c][n] = (P @ V)[n][c] : per-batch M=1024(tokens), N=768(chan),
    //    K=1024, transposed store folds the swapaxes+reshape
    sgemm128<false, true, false><<<dim3(768 / 128, 1024 / 128, 32), 256>>>(
        sc, qkv + 1536, nullptr, ot, 1024, 1024, 2304, 1024, 1.0f,
        1024L * 1024, 1024L * 2304, 768L * 1024);

    // 5) out = A2 @ proj_w + proj_b : M=32768, N=768, K=768 (NN + bias)
    //    A2 is the OT buffer reinterpreted row-major (N,C) — exactly the
    //    reference's swapaxes(1,2).reshape(B,N,C).
    sgemm128<false, false, true><<<dim3(768 / 128, 32768 / 128, 1), 256>>>(
        ot, proj_w, proj_b, out, 768, 768, 768, 768, 1.0f, 0, 0, 0);
}